// round 5
// baseline (speedup 1.0000x reference)
#include <cuda_runtime.h>

#define RREL  3
#define EMBD  32
#define HIDD  64
#define NMAX  300000
#define EMAX  1500000
#define GMAX  30000
#define TROWS 164   // 26 shape + 10 col + 128 pos

// ---------------- scratch (static device memory; no allocs) ----------------
__device__ float g_h1[(size_t)NMAX * HIDD];            // relu(layer1 out)
__device__ float g_inv[NMAX * RREL];                   // 1/max(cnt,1) per (node, rel)
__device__ int   g_cnt[NMAX * RREL];
__device__ int   g_base[NMAX];                         // CSR row start
__device__ int   g_fill[NMAX];                         // CSR fill cursor (== deg after place)
__device__ int   g_gcnt[GMAX];
__device__ float g_ginv[GMAX];
__device__ int   g_ctr[1];
__device__ unsigned long long g_edge[EMAX];            // lo: src|rel<<20 ; hi: si|ci<<5|pi<<9|rel<<16
__device__ float g_tabRoot[TROWS * HIDD];              // emb-row @ root1
__device__ float g_tabRel[RREL * TROWS * HIDD];        // emb-row @ W1[r]

__device__ __forceinline__ void red_add_v2(float* p, float a, float b) {
    asm volatile("red.global.add.v2.f32 [%0], {%1,%2};"
                 :: "l"(p), "f"(a), "f"(b) : "memory");
}

// ---------------- kernels ----------------
__global__ void k_zero(int N, int G) {
    int t = blockIdx.x * blockDim.x + threadIdx.x;
    if (t < N * RREL) g_cnt[t] = 0;
    if (t < N)        g_fill[t] = 0;
    if (t < G)        g_gcnt[t] = 0;
    if (t == 0)       g_ctr[0] = 0;
}

__global__ void k_cnt(const int* __restrict__ ei, const int* __restrict__ et, int E) {
    int e = blockIdx.x * blockDim.x + threadIdx.x;
    if (e >= E) return;
    atomicAdd(&g_cnt[ei[E + e] * RREL + et[e]], 1);
}

// Per node: inv weights, graph counts, and CSR base via warp-aggregated atomic.
__global__ void k_base(const int* __restrict__ batch, int N) {
    int t    = blockIdx.x * blockDim.x + threadIdx.x;
    int lane = threadIdx.x & 31;
    int deg  = 0;
    if (t < N) {
        int c0 = g_cnt[3 * t], c1 = g_cnt[3 * t + 1], c2 = g_cnt[3 * t + 2];
        deg = c0 + c1 + c2;
        g_inv[3 * t + 0] = 1.0f / (float)(c0 > 0 ? c0 : 1);
        g_inv[3 * t + 1] = 1.0f / (float)(c1 > 0 ? c1 : 1);
        g_inv[3 * t + 2] = 1.0f / (float)(c2 > 0 ? c2 : 1);
        atomicAdd(&g_gcnt[batch[t]], 1);
    }
    int incl = deg;
    #pragma unroll
    for (int off = 1; off < 32; off <<= 1) {
        int v = __shfl_up_sync(0xffffffffu, incl, off);
        if (lane >= off) incl += v;
    }
    int total = __shfl_sync(0xffffffffu, incl, 31);
    int base = 0;
    if (lane == 31 && total > 0) base = atomicAdd(&g_ctr[0], total);
    base = __shfl_sync(0xffffffffu, base, 31);
    if (t < N) g_base[t] = base + incl - deg;
}

__global__ void k_place(const int* __restrict__ ei, const int* __restrict__ et,
                        const int* __restrict__ sid, const int* __restrict__ cid,
                        const int* __restrict__ pid, int E) {
    int e = blockIdx.x * blockDim.x + threadIdx.x;
    if (e >= E) return;
    int s = ei[e], d = ei[E + e], r = et[e];
    int pos = g_base[d] + atomicAdd(&g_fill[d], 1);
    unsigned lo = (unsigned)s | ((unsigned)r << 20);
    unsigned hi = (unsigned)sid[s] | ((unsigned)cid[s] << 5)
                | ((unsigned)pid[s] << 9) | ((unsigned)r << 16);
    g_edge[pos] = (unsigned long long)lo | ((unsigned long long)hi << 32);
}

// tabRoot[row][j] = emb(row) . root1[:,j] ; tabRel[r][row][j] = emb(row) . W1[r][:,j]
__global__ void k_tab(const float* __restrict__ se, const float* __restrict__ ce,
                      const float* __restrict__ pe, const float* __restrict__ W1,
                      const float* __restrict__ root1) {
    int t = blockIdx.x * blockDim.x + threadIdx.x;
    if (t >= 4 * TROWS * HIDD) return;
    int j   = t % HIDD;
    int row = (t / HIDD) % TROWS;
    int rel = t / (HIDD * TROWS);  // 0 = root, 1..3 = relations
    const float* emb; int er;
    if (row < 26)      { emb = se; er = row; }
    else if (row < 36) { emb = ce; er = row - 26; }
    else               { emb = pe; er = row - 36; }
    const float* w = (rel == 0) ? (root1 + j) : (W1 + (size_t)(rel - 1) * EMBD * HIDD + j);
    float s = 0.f;
    #pragma unroll
    for (int k = 0; k < EMBD; k++) s += emb[er * EMBD + k] * w[k * HIDD];
    if (rel == 0) g_tabRoot[row * HIDD + j] = s;
    else          g_tabRel[((rel - 1) * TROWS + row) * HIDD + j] = s;
}

// Layer 1: warp per dst node, lane covers 2 feature cols; stores relu(h1).
__global__ void k_agg1(const int* __restrict__ sid, const int* __restrict__ cid,
                       const int* __restrict__ pid, const float* __restrict__ b1, int N) {
    int lane = threadIdx.x & 31;
    int d = blockIdx.x * (blockDim.x >> 5) + (threadIdx.x >> 5);
    if (d >= N) return;
    int j  = lane * 2;
    int e0 = g_base[d], e1 = e0 + g_fill[d];
    float2 acc = {0.f, 0.f};
    const uint2* ge = (const uint2*)g_edge;
    for (int e = e0; e < e1; e++) {
        unsigned p = ge[e].y;
        int si  = p & 31;
        int ci  = (p >> 5) & 15;
        int pi  = (p >> 9) & 127;
        int rel = (int)(p >> 16);
        float w = g_inv[3 * d + rel];
        const float* tb = g_tabRel + (size_t)rel * (TROWS * HIDD);
        float2 m0 = *(const float2*)&tb[si * HIDD + j];
        float2 m1 = *(const float2*)&tb[(26 + ci) * HIDD + j];
        float2 m2 = *(const float2*)&tb[(36 + pi) * HIDD + j];
        acc.x += w * (m0.x + m1.x + m2.x);
        acc.y += w * (m0.y + m1.y + m2.y);
    }
    int si = sid[d], ci = cid[d], pi = pid[d];
    float2 r0 = *(const float2*)&g_tabRoot[si * HIDD + j];
    float2 r1 = *(const float2*)&g_tabRoot[(26 + ci) * HIDD + j];
    float2 r2 = *(const float2*)&g_tabRoot[(36 + pi) * HIDD + j];
    float2 bv = *(const float2*)&b1[j];
    float hx = acc.x + r0.x + r1.x + r2.x + bv.x;
    float hy = acc.y + r0.y + r1.y + r2.y + bv.y;
    float2 o;
    o.x = hx > 0.f ? hx : 0.f;
    o.y = hy > 0.f ? hy : 0.f;
    *(float2*)&g_h1[(size_t)d * HIDD + j] = o;
}

__global__ void k_outinit(const float* __restrict__ lin_b, float* __restrict__ out, int G) {
    int g = blockIdx.x * blockDim.x + threadIdx.x;
    if (g >= G) return;
    out[2 * g + 0] = lin_b[0];
    out[2 * g + 1] = lin_b[1];
    int c = g_gcnt[g];
    g_ginv[g] = 1.0f / (float)(c > 0 ? c : 1);
}

// Fused layer-2 + pooling head.
// Per block: 128 nodes. K = 256 in 8 chunks of 32:
//   chunks 0-1: A = relu(h1[node][k])           (direct load)
//   chunks 2-7: A = mean_{r}(relu(h1[src][k]))  (aggregated in smem; rel = (ph-2)/2, half = (ph-2)&1)
// B chunk = root2 (k<64) or W2[rel]. After K loop: v = acc + b2, relu,
// project with lin_W, shuffle-reduce over col groups, red.v2 into out.
#define ASP 132  // 128 + 4 (k-row stride, 16B aligned)
#define BSP 68   // 64 + 4
__global__ __launch_bounds__(128, 4) void k_gemm_fused(
        const float* __restrict__ root2, const float* __restrict__ W2,
        const float* __restrict__ b2, const float* __restrict__ linW,
        const int* __restrict__ batch, float* __restrict__ out, int N) {
    __shared__ float As[32 * ASP];   // [k][node]
    __shared__ float Bs[32 * BSP];   // [k][col]
    int i0  = blockIdx.x * 128;
    int tid = threadIdx.x;
    int cg  = tid & 7;    // col group: cols cg*8 .. cg*8+7
    int ng  = tid >> 3;   // node group: nodes ng*8 .. ng*8+7 (4 pairs)
    int wrp = tid >> 5, lane = tid & 31;

    unsigned long long acc[32];      // acc[p*8+c] = f32x2 over node pair p, col c
    #pragma unroll
    for (int i = 0; i < 32; i++) acc[i] = 0ull;

    const uint2* ge = (const uint2*)g_edge;

    for (int ph = 0; ph < 8; ph++) {
        int kk0 = ph * 32;
        __syncthreads();
        // ---- load B chunk [32 x 64] ----
        #pragma unroll
        for (int t = 0; t < 16; t++) {
            int idx = tid + t * 128;
            int k = idx >> 6, c = idx & 63;
            int kk = kk0 + k;
            float w;
            if (kk < 64) w = root2[kk * HIDD + c];
            else {
                int kr = kk - 64;
                w = W2[((size_t)(kr >> 6) * HIDD + (kr & 63)) * HIDD + c];
            }
            Bs[k * BSP + c] = w;
        }
        // ---- fill A chunk [32 k][128 node] ----
        if (ph < 2) {
            // direct: thread per node, row load + column stores
            int node = tid;
            int gi = i0 + node;
            float4 buf[8];
            if (gi < N) {
                const float4* row = (const float4*)&g_h1[(size_t)gi * HIDD + kk0];
                #pragma unroll
                for (int q = 0; q < 8; q++) buf[q] = row[q];
            } else {
                #pragma unroll
                for (int q = 0; q < 8; q++) buf[q] = make_float4(0.f, 0.f, 0.f, 0.f);
            }
            #pragma unroll
            for (int q = 0; q < 8; q++) {
                As[(4 * q + 0) * ASP + node] = buf[q].x;
                As[(4 * q + 1) * ASP + node] = buf[q].y;
                As[(4 * q + 2) * ASP + node] = buf[q].z;
                As[(4 * q + 3) * ASP + node] = buf[q].w;
            }
        } else {
            int rel  = (ph - 2) >> 1;
            int hofs = ((ph - 2) & 1) * 32;
            for (int it = 0; it < 32; it++) {
                int node = wrp * 32 + it;
                int gi = i0 + node;
                float a = 0.f;
                if (gi < N) {
                    int e0 = g_base[gi], e1 = e0 + g_fill[gi];
                    float inv = g_inv[3 * gi + rel];
                    for (int e = e0; e < e1; e++) {
                        unsigned lo = ge[e].x;
                        if ((int)(lo >> 20) == rel) {
                            int src = lo & 0xFFFFF;
                            a += g_h1[(size_t)src * HIDD + hofs + lane];
                        }
                    }
                    a *= inv;
                }
                As[lane * ASP + node] = a;
            }
        }
        __syncthreads();
        // ---- FMA over 32 k ----
        #pragma unroll 8
        for (int k = 0; k < 32; k++) {
            const ulonglong2* ap = (const ulonglong2*)&As[k * ASP + ng * 8];
            ulonglong2 A0 = ap[0], A1 = ap[1];
            float4 bv0 = *(const float4*)&Bs[k * BSP + cg * 8];
            float4 bv1 = *(const float4*)&Bs[k * BSP + cg * 8 + 4];
            unsigned long long bd[8];
            asm("mov.b64 %0, {%1,%1};" : "=l"(bd[0]) : "f"(bv0.x));
            asm("mov.b64 %0, {%1,%1};" : "=l"(bd[1]) : "f"(bv0.y));
            asm("mov.b64 %0, {%1,%1};" : "=l"(bd[2]) : "f"(bv0.z));
            asm("mov.b64 %0, {%1,%1};" : "=l"(bd[3]) : "f"(bv0.w));
            asm("mov.b64 %0, {%1,%1};" : "=l"(bd[4]) : "f"(bv1.x));
            asm("mov.b64 %0, {%1,%1};" : "=l"(bd[5]) : "f"(bv1.y));
            asm("mov.b64 %0, {%1,%1};" : "=l"(bd[6]) : "f"(bv1.z));
            asm("mov.b64 %0, {%1,%1};" : "=l"(bd[7]) : "f"(bv1.w));
            unsigned long long ap4[4] = {A0.x, A0.y, A1.x, A1.y};
            #pragma unroll
            for (int p = 0; p < 4; p++)
                #pragma unroll
                for (int c = 0; c < 8; c++)
                    asm("fma.rn.f32x2 %0, %1, %2, %0;"
                        : "+l"(acc[p * 8 + c]) : "l"(ap4[p]), "l"(bd[c]));
        }
    }

    // ---- epilogue: +b2, relu, lin_W projection, reduce over cg, pool ----
    float4 bb0 = *(const float4*)&b2[cg * 8];
    float4 bb1 = *(const float4*)&b2[cg * 8 + 4];
    float bb[8] = {bb0.x, bb0.y, bb0.z, bb0.w, bb1.x, bb1.y, bb1.z, bb1.w};
    float lw0[8], lw1[8];
    #pragma unroll
    for (int c = 0; c < 8; c++) {
        lw0[c] = linW[(cg * 8 + c) * 2];
        lw1[c] = linW[(cg * 8 + c) * 2 + 1];
    }
    float o0[8], o1[8];
    #pragma unroll
    for (int p = 0; p < 4; p++) {
        float s0l = 0.f, s1l = 0.f, s0h = 0.f, s1h = 0.f;
        #pragma unroll
        for (int c = 0; c < 8; c++) {
            float vl, vh;
            asm("mov.b64 {%0, %1}, %2;" : "=f"(vl), "=f"(vh) : "l"(acc[p * 8 + c]));
            vl += bb[c]; vh += bb[c];
            vl = vl > 0.f ? vl : 0.f;
            vh = vh > 0.f ? vh : 0.f;
            s0l += vl * lw0[c]; s1l += vl * lw1[c];
            s0h += vh * lw0[c]; s1h += vh * lw1[c];
        }
        o0[2 * p] = s0l; o1[2 * p] = s1l;
        o0[2 * p + 1] = s0h; o1[2 * p + 1] = s1h;
    }
    #pragma unroll
    for (int m = 1; m < 8; m <<= 1) {
        #pragma unroll
        for (int n = 0; n < 8; n++) {
            o0[n] += __shfl_xor_sync(0xffffffffu, o0[n], m);
            o1[n] += __shfl_xor_sync(0xffffffffu, o1[n], m);
        }
    }
    if (cg == 0) {
        #pragma unroll
        for (int n = 0; n < 8; n++) {
            int gi = i0 + ng * 8 + n;
            if (gi < N) {
                int b = batch[gi];
                float gw = g_ginv[b];
                red_add_v2(&out[2 * b], o0[n] * gw, o1[n] * gw);
            }
        }
    }
}

// ---------------- launch ----------------
extern "C" void kernel_launch(void* const* d_in, const int* in_sizes, int n_in,
                              void* d_out, int out_size) {
    const int* sid = (const int*)d_in[0];
    const int* cid = (const int*)d_in[1];
    const int* pid = (const int*)d_in[2];
    const int* ei  = (const int*)d_in[3];
    const int* et  = (const int*)d_in[4];
    const int* bat = (const int*)d_in[5];
    int off = (in_sizes[6] == 1) ? 7 : 6;
    const float* se    = (const float*)d_in[off + 0];
    const float* ce    = (const float*)d_in[off + 1];
    const float* pe    = (const float*)d_in[off + 2];
    const float* W1    = (const float*)d_in[off + 3];
    const float* root1 = (const float*)d_in[off + 4];
    const float* b1    = (const float*)d_in[off + 5];
    const float* W2    = (const float*)d_in[off + 6];
    const float* root2 = (const float*)d_in[off + 7];
    const float* b2    = (const float*)d_in[off + 8];
    const float* linW  = (const float*)d_in[off + 9];
    const float* linb  = (const float*)d_in[off + 10];
    float* out = (float*)d_out;

    int N = in_sizes[0];
    int E = in_sizes[4];
    int G = out_size / 2;
    const int TB = 256;

    k_zero<<<(N * RREL + TB - 1) / TB, TB>>>(N, G);
    k_cnt<<<(E + TB - 1) / TB, TB>>>(ei, et, E);
    k_base<<<(N + TB - 1) / TB, TB>>>(bat, N);
    k_place<<<(E + TB - 1) / TB, TB>>>(ei, et, sid, cid, pid, E);   // <- profiled slot
    k_tab<<<(4 * TROWS * HIDD + TB - 1) / TB, TB>>>(se, ce, pe, W1, root1);
    k_agg1<<<(N * 32 + TB - 1) / TB, TB>>>(sid, cid, pid, b1, N);
    k_outinit<<<(G + TB - 1) / TB, TB>>>(linb, out, G);
    k_gemm_fused<<<(N + 127) / 128, 128>>>(root2, W2, b2, linW, bat, out, N);
}

// round 8
// speedup vs baseline: 1.5871x; 1.5871x over previous
#include <cuda_runtime.h>

#define RREL  3
#define EMBD  32
#define HIDD  64
#define NMAX  300000
#define EMAX  1500000
#define GMAX  30000
#define TROWS 164   // 26 shape + 10 col + 128 pos

// ---------------- scratch (static device memory; no allocs) ----------------
__device__ float g_h1[(size_t)NMAX * HIDD];            // relu(layer1 out)
__device__ float g_agg[(size_t)NMAX * RREL * HIDD];    // per-rel aggregated relu(h1)
__device__ float g_inv[NMAX * RREL];                   // 1/max(cnt,1) per (node, rel)
__device__ int   g_cnt[NMAX * RREL];
__device__ int   g_base[NMAX];                         // CSR row start
__device__ int   g_fill[NMAX];                         // CSR fill cursor (== deg after place)
__device__ int   g_gcnt[GMAX];
__device__ float g_ginv[GMAX];
__device__ int   g_ctr[1];
__device__ unsigned long long g_edge[EMAX];            // lo: src|rel<<20 ; hi: si|ci<<5|pi<<9|rel<<16
__device__ float g_tabRoot[TROWS * HIDD];              // emb-row @ root1
__device__ float g_tabRel[RREL * TROWS * HIDD];        // emb-row @ W1[r]

__device__ __forceinline__ void red_add_v2(float* p, float a, float b) {
    asm volatile("red.global.add.v2.f32 [%0], {%1,%2};"
                 :: "l"(p), "f"(a), "f"(b) : "memory");
}

// ---------------- kernels ----------------
__global__ void k_zero(int N, int G) {
    int t = blockIdx.x * blockDim.x + threadIdx.x;
    if (t < N * RREL) g_cnt[t] = 0;
    if (t < N)        g_fill[t] = 0;
    if (t < G)        g_gcnt[t] = 0;
    if (t == 0)       g_ctr[0] = 0;
}

__global__ void k_cnt(const int* __restrict__ ei, const int* __restrict__ et, int E) {
    int e = blockIdx.x * blockDim.x + threadIdx.x;
    if (e >= E) return;
    atomicAdd(&g_cnt[ei[E + e] * RREL + et[e]], 1);
}

// Per node: inv weights, graph counts, and CSR base via warp-aggregated atomic.
__global__ void k_base(const int* __restrict__ batch, int N) {
    int t    = blockIdx.x * blockDim.x + threadIdx.x;
    int lane = threadIdx.x & 31;
    int deg  = 0;
    if (t < N) {
        int c0 = g_cnt[3 * t], c1 = g_cnt[3 * t + 1], c2 = g_cnt[3 * t + 2];
        deg = c0 + c1 + c2;
        g_inv[3 * t + 0] = 1.0f / (float)(c0 > 0 ? c0 : 1);
        g_inv[3 * t + 1] = 1.0f / (float)(c1 > 0 ? c1 : 1);
        g_inv[3 * t + 2] = 1.0f / (float)(c2 > 0 ? c2 : 1);
        atomicAdd(&g_gcnt[batch[t]], 1);
    }
    int incl = deg;
    #pragma unroll
    for (int off = 1; off < 32; off <<= 1) {
        int v = __shfl_up_sync(0xffffffffu, incl, off);
        if (lane >= off) incl += v;
    }
    int total = __shfl_sync(0xffffffffu, incl, 31);
    int base = 0;
    if (lane == 31 && total > 0) base = atomicAdd(&g_ctr[0], total);
    base = __shfl_sync(0xffffffffu, base, 31);
    if (t < N) g_base[t] = base + incl - deg;
}

__global__ void k_place(const int* __restrict__ ei, const int* __restrict__ et,
                        const int* __restrict__ sid, const int* __restrict__ cid,
                        const int* __restrict__ pid, int E) {
    int e = blockIdx.x * blockDim.x + threadIdx.x;
    if (e >= E) return;
    int s = ei[e], d = ei[E + e], r = et[e];
    int pos = g_base[d] + atomicAdd(&g_fill[d], 1);
    unsigned lo = (unsigned)s | ((unsigned)r << 20);
    unsigned hi = (unsigned)sid[s] | ((unsigned)cid[s] << 5)
                | ((unsigned)pid[s] << 9) | ((unsigned)r << 16);
    g_edge[pos] = (unsigned long long)lo | ((unsigned long long)hi << 32);
}

// tabRoot[row][j] = emb(row) . root1[:,j] ; tabRel[r][row][j] = emb(row) . W1[r][:,j]
__global__ void k_tab(const float* __restrict__ se, const float* __restrict__ ce,
                      const float* __restrict__ pe, const float* __restrict__ W1,
                      const float* __restrict__ root1) {
    int t = blockIdx.x * blockDim.x + threadIdx.x;
    if (t >= 4 * TROWS * HIDD) return;
    int j   = t % HIDD;
    int row = (t / HIDD) % TROWS;
    int rel = t / (HIDD * TROWS);  // 0 = root, 1..3 = relations
    const float* emb; int er;
    if (row < 26)      { emb = se; er = row; }
    else if (row < 36) { emb = ce; er = row - 26; }
    else               { emb = pe; er = row - 36; }
    const float* w = (rel == 0) ? (root1 + j) : (W1 + (size_t)(rel - 1) * EMBD * HIDD + j);
    float s = 0.f;
    #pragma unroll
    for (int k = 0; k < EMBD; k++) s += emb[er * EMBD + k] * w[k * HIDD];
    if (rel == 0) g_tabRoot[row * HIDD + j] = s;
    else          g_tabRel[((rel - 1) * TROWS + row) * HIDD + j] = s;
}

// Layer 1: warp per dst node, lane covers 2 feature cols; stores relu(h1).
__global__ void k_agg1(const int* __restrict__ sid, const int* __restrict__ cid,
                       const int* __restrict__ pid, const float* __restrict__ b1, int N) {
    int lane = threadIdx.x & 31;
    int d = blockIdx.x * (blockDim.x >> 5) + (threadIdx.x >> 5);
    if (d >= N) return;
    int j  = lane * 2;
    int e0 = g_base[d], e1 = e0 + g_fill[d];
    float2 acc = {0.f, 0.f};
    const uint2* ge = (const uint2*)g_edge;
    for (int e = e0; e < e1; e++) {
        unsigned p = ge[e].y;
        int si  = p & 31;
        int ci  = (p >> 5) & 15;
        int pi  = (p >> 9) & 127;
        int rel = (int)(p >> 16);
        float w = g_inv[3 * d + rel];
        const float* tb = g_tabRel + (size_t)rel * (TROWS * HIDD);
        float2 m0 = *(const float2*)&tb[si * HIDD + j];
        float2 m1 = *(const float2*)&tb[(26 + ci) * HIDD + j];
        float2 m2 = *(const float2*)&tb[(36 + pi) * HIDD + j];
        acc.x += w * (m0.x + m1.x + m2.x);
        acc.y += w * (m0.y + m1.y + m2.y);
    }
    int si = sid[d], ci = cid[d], pi = pid[d];
    float2 r0 = *(const float2*)&g_tabRoot[si * HIDD + j];
    float2 r1 = *(const float2*)&g_tabRoot[(26 + ci) * HIDD + j];
    float2 r2 = *(const float2*)&g_tabRoot[(36 + pi) * HIDD + j];
    float2 bv = *(const float2*)&b1[j];
    float hx = acc.x + r0.x + r1.x + r2.x + bv.x;
    float hy = acc.y + r0.y + r1.y + r2.y + bv.y;
    float2 o;
    o.x = hx > 0.f ? hx : 0.f;
    o.y = hy > 0.f ? hy : 0.f;
    *(float2*)&g_h1[(size_t)d * HIDD + j] = o;
}

__global__ void k_outinit(const float* __restrict__ lin_b, float* __restrict__ out, int G) {
    int g = blockIdx.x * blockDim.x + threadIdx.x;
    if (g >= G) return;
    out[2 * g + 0] = lin_b[0];
    out[2 * g + 1] = lin_b[1];
    int c = g_gcnt[g];
    g_ginv[g] = 1.0f / (float)(c > 0 ? c : 1);
}

// Layer 2 feature aggregation (pre-transform): agg[d][r][:] = sum_{e in N_r(d)} w * h1[src]
__global__ void k_agg2(int N) {
    int lane = threadIdx.x & 31;
    int d = blockIdx.x * (blockDim.x >> 5) + (threadIdx.x >> 5);
    if (d >= N) return;
    int j  = lane * 2;
    int e0 = g_base[d], e1 = e0 + g_fill[d];
    float2 a0 = {0.f, 0.f}, a1 = {0.f, 0.f}, a2 = {0.f, 0.f};
    const uint2* ge = (const uint2*)g_edge;
    for (int e = e0; e < e1; e++) {
        unsigned p = ge[e].x;
        int src = p & 0xFFFFF, rel = (int)(p >> 20);
        float w = g_inv[3 * d + rel];
        float2 v = *(const float2*)&g_h1[(size_t)src * HIDD + j];
        float vx = v.x * w, vy = v.y * w;
        if (rel == 0)      { a0.x += vx; a0.y += vy; }
        else if (rel == 1) { a1.x += vx; a1.y += vy; }
        else               { a2.x += vx; a2.y += vy; }
    }
    float* dst = g_agg + (size_t)d * (RREL * HIDD);
    *(float2*)&dst[j]       = a0;
    *(float2*)&dst[64 + j]  = a1;
    *(float2*)&dst[128 + j] = a2;
}

// Layer-2 GEMM + fused pooling head.
// h2[i][:] = [relu(h1)|agg](i, 0:256) @ [root2; W2_r] + b2; then relu, @lin_W,
// scaled by 1/graph_cnt, red.v2 into out.
// Block: 128 nodes, 128 threads; thread = (ng: 8 nodes as 4 f32x2 pairs) x (cg: 8 cols).
#define ASP 132  // 128 + 4 (k-row stride)
#define BSP 68   // 64 + 4
__global__ __launch_bounds__(128, 4) void k_gemm_fused(
        const float* __restrict__ root2, const float* __restrict__ W2,
        const float* __restrict__ b2, const float* __restrict__ linW,
        const int* __restrict__ batch, float* __restrict__ out, int N) {
    __shared__ float As[32 * ASP];   // [k][node]
    __shared__ float Bs[32 * BSP];   // [k][col]
    int i0  = blockIdx.x * 128;
    int tid = threadIdx.x;
    int cg  = tid & 7;    // col group: cols cg*8 .. cg*8+7
    int ng  = tid >> 3;   // node group: nodes ng*8 .. ng*8+7 (4 f32x2 pairs)

    unsigned long long acc[32];      // acc[p*8+c]
    #pragma unroll
    for (int i = 0; i < 32; i++) acc[i] = 0ull;

    for (int ph = 0; ph < 8; ph++) {
        int kk0 = ph * 32;
        __syncthreads();
        // ---- load B chunk [32 x 64] ----
        #pragma unroll
        for (int t = 0; t < 16; t++) {
            int idx = tid + t * 128;
            int k = idx >> 6, c = idx & 63;
            int kk = kk0 + k;
            float w;
            if (kk < 64) w = root2[kk * HIDD + c];
            else {
                int kr = kk - 64;
                w = W2[((size_t)(kr >> 6) * HIDD + (kr & 63)) * HIDD + c];
            }
            Bs[k * BSP + c] = w;
        }
        // ---- fill A chunk [32 k][128 node]: thread per node, contiguous row load ----
        {
            int node = tid;
            int gi = i0 + node;
            float4 buf[8];
            if (gi < N) {
                const float4* row;
                if (ph < 2) row = (const float4*)&g_h1[(size_t)gi * HIDD + kk0];
                else        row = (const float4*)&g_agg[(size_t)gi * (RREL * HIDD) + (kk0 - 64)];
                #pragma unroll
                for (int q = 0; q < 8; q++) buf[q] = row[q];
            } else {
                #pragma unroll
                for (int q = 0; q < 8; q++) buf[q] = make_float4(0.f, 0.f, 0.f, 0.f);
            }
            #pragma unroll
            for (int q = 0; q < 8; q++) {
                As[(4 * q + 0) * ASP + node] = buf[q].x;
                As[(4 * q + 1) * ASP + node] = buf[q].y;
                As[(4 * q + 2) * ASP + node] = buf[q].z;
                As[(4 * q + 3) * ASP + node] = buf[q].w;
            }
        }
        __syncthreads();
        // ---- FMA over 32 k ----
        #pragma unroll 8
        for (int k = 0; k < 32; k++) {
            const ulonglong2* ap = (const ulonglong2*)&As[k * ASP + ng * 8];
            ulonglong2 A0 = ap[0], A1 = ap[1];
            float4 bv0 = *(const float4*)&Bs[k * BSP + cg * 8];
            float4 bv1 = *(const float4*)&Bs[k * BSP + cg * 8 + 4];
            unsigned long long bd[8];
            asm("mov.b64 %0, {%1,%1};" : "=l"(bd[0]) : "f"(bv0.x));
            asm("mov.b64 %0, {%1,%1};" : "=l"(bd[1]) : "f"(bv0.y));
            asm("mov.b64 %0, {%1,%1};" : "=l"(bd[2]) : "f"(bv0.z));
            asm("mov.b64 %0, {%1,%1};" : "=l"(bd[3]) : "f"(bv0.w));
            asm("mov.b64 %0, {%1,%1};" : "=l"(bd[4]) : "f"(bv1.x));
            asm("mov.b64 %0, {%1,%1};" : "=l"(bd[5]) : "f"(bv1.y));
            asm("mov.b64 %0, {%1,%1};" : "=l"(bd[6]) : "f"(bv1.z));
            asm("mov.b64 %0, {%1,%1};" : "=l"(bd[7]) : "f"(bv1.w));
            unsigned long long ap4[4] = {A0.x, A0.y, A1.x, A1.y};
            #pragma unroll
            for (int p = 0; p < 4; p++)
                #pragma unroll
                for (int c = 0; c < 8; c++)
                    asm("fma.rn.f32x2 %0, %1, %2, %0;"
                        : "+l"(acc[p * 8 + c]) : "l"(ap4[p]), "l"(bd[c]));
        }
    }

    // ---- epilogue: +b2, relu, lin_W projection, reduce over cg, pool ----
    float4 bb0 = *(const float4*)&b2[cg * 8];
    float4 bb1 = *(const float4*)&b2[cg * 8 + 4];
    float bb[8] = {bb0.x, bb0.y, bb0.z, bb0.w, bb1.x, bb1.y, bb1.z, bb1.w};
    float lw0[8], lw1[8];
    #pragma unroll
    for (int c = 0; c < 8; c++) {
        lw0[c] = linW[(cg * 8 + c) * 2];
        lw1[c] = linW[(cg * 8 + c) * 2 + 1];
    }
    float o0[8], o1[8];
    #pragma unroll
    for (int p = 0; p < 4; p++) {
        float s0l = 0.f, s1l = 0.f, s0h = 0.f, s1h = 0.f;
        #pragma unroll
        for (int c = 0; c < 8; c++) {
            float vl, vh;
            asm("mov.b64 {%0, %1}, %2;" : "=f"(vl), "=f"(vh) : "l"(acc[p * 8 + c]));
            vl += bb[c]; vh += bb[c];
            vl = vl > 0.f ? vl : 0.f;
            vh = vh > 0.f ? vh : 0.f;
            s0l += vl * lw0[c]; s1l += vl * lw1[c];
            s0h += vh * lw0[c]; s1h += vh * lw1[c];
        }
        o0[2 * p] = s0l; o1[2 * p] = s1l;
        o0[2 * p + 1] = s0h; o1[2 * p + 1] = s1h;
    }
    #pragma unroll
    for (int m = 1; m < 8; m <<= 1) {
        #pragma unroll
        for (int n = 0; n < 8; n++) {
            o0[n] += __shfl_xor_sync(0xffffffffu, o0[n], m);
            o1[n] += __shfl_xor_sync(0xffffffffu, o1[n], m);
        }
    }
    if (cg == 0) {
        #pragma unroll
        for (int n = 0; n < 8; n++) {
            int gi = i0 + ng * 8 + n;
            if (gi < N) {
                int b = batch[gi];
                float gw = g_ginv[b];
                red_add_v2(&out[2 * b], o0[n] * gw, o1[n] * gw);
            }
        }
    }
}

// ---------------- launch ----------------
extern "C" void kernel_launch(void* const* d_in, const int* in_sizes, int n_in,
                              void* d_out, int out_size) {
    const int* sid = (const int*)d_in[0];
    const int* cid = (const int*)d_in[1];
    const int* pid = (const int*)d_in[2];
    const int* ei  = (const int*)d_in[3];
    const int* et  = (const int*)d_in[4];
    const int* bat = (const int*)d_in[5];
    int off = (in_sizes[6] == 1) ? 7 : 6;
    const float* se    = (const float*)d_in[off + 0];
    const float* ce    = (const float*)d_in[off + 1];
    const float* pe    = (const float*)d_in[off + 2];
    const float* W1    = (const float*)d_in[off + 3];
    const float* root1 = (const float*)d_in[off + 4];
    const float* b1    = (const float*)d_in[off + 5];
    const float* W2    = (const float*)d_in[off + 6];
    const float* root2 = (const float*)d_in[off + 7];
    const float* b2    = (const float*)d_in[off + 8];
    const float* linW  = (const float*)d_in[off + 9];
    const float* linb  = (const float*)d_in[off + 10];
    float* out = (float*)d_out;

    int N = in_sizes[0];
    int E = in_sizes[4];
    int G = out_size / 2;
    const int TB = 256;

    k_zero<<<(N * RREL + TB - 1) / TB, TB>>>(N, G);
    k_cnt<<<(E + TB - 1) / TB, TB>>>(ei, et, E);
    k_base<<<(N + TB - 1) / TB, TB>>>(bat, N);
    k_place<<<(E + TB - 1) / TB, TB>>>(ei, et, sid, cid, pid, E);   // <- profiled slot (4th)
    k_tab<<<(4 * TROWS * HIDD + TB - 1) / TB, TB>>>(se, ce, pe, W1, root1);
    k_agg1<<<(N * 32 + TB - 1) / TB, TB>>>(sid, cid, pid, b1, N);
    k_outinit<<<(G + TB - 1) / TB, TB>>>(linb, out, G);
    k_agg2<<<(N * 32 + TB - 1) / TB, TB>>>(N);
    k_gemm_fused<<<(N + 127) / 128, 128>>>(root2, W2, b2, linW, bat, out, N);
}